// round 1
// baseline (speedup 1.0000x reference)
#include <cuda_runtime.h>
#include <cstdint>

// Problem constants
#define B_   8
#define N_   2048
#define F0_  128
#define HID_ 64
#define OUT_ 16
#define K_   10

// ---------------- device scratch (static; no allocation) ----------------
__device__ float g_z[2][N_];          // ping-pong (I-L^T)^k 1 chain
__device__ float g_r[2][N_];          // ping-pong Horner accumulator
__device__ float g_a[K_ + 1];         // a_i = theta_i * C(K,i)
__device__ float g_part[B_][32][HID_];// per-(b,chunk) partial Hg sums

__constant__ float c_binom[K_ + 1] = {1.f, 10.f, 45.f, 120.f, 210.f, 252.f,
                                      210.f, 120.f, 45.f, 10.f, 1.f};

// ---------------- setup: init z0 = 1, r0 = a_K * 1, coefficients --------
__global__ void setup_kernel(const float* __restrict__ theta) {
    int i = blockIdx.x * 1024 + threadIdx.x;
    if (i < N_) {
        g_z[0][i] = 1.0f;
        g_r[0][i] = theta[K_];   // a_K = theta_K * C(K,K) = theta_K
    }
    if (i < K_ + 1) g_a[i] = theta[i] * c_binom[i];
}

// ---------------- one fused filter pass ---------------------------------
// z_out = z_in - L^T z_in ;  r_out = L^T r_in + a[coefIdx] * z_out
// (L^T x)[w] = sum_v L[v*N + w] * x[v]  -> coalesced over w.
// grid: 256 blocks (8 w-columns each), block dim3(8,32): tx=w lane, ty=v group.
__global__ void pass_kernel(const float* __restrict__ L, int pin, int coefIdx) {
    __shared__ float sz[N_];
    __shared__ float sr[N_];
    __shared__ float redz[32][8];
    __shared__ float redr[32][8];

    const float* zin = g_z[pin];
    const float* rin = g_r[pin];
    float* zout = g_z[pin ^ 1];
    float* rout = g_r[pin ^ 1];

    int tx = threadIdx.x;            // 0..7
    int ty = threadIdx.y;            // 0..31
    int tid = ty * 8 + tx;

    for (int i = tid; i < N_; i += 256) { sz[i] = zin[i]; sr[i] = rin[i]; }
    __syncthreads();

    int w = blockIdx.x * 8 + tx;
    const float* Lp = L + w;
    float az = 0.f, ar = 0.f;
#pragma unroll 8
    for (int v = ty; v < N_; v += 32) {
        float lv = Lp[v * N_];
        az += lv * sz[v];
        ar += lv * sr[v];
    }
    redz[ty][tx] = az;
    redr[ty][tx] = ar;
    __syncthreads();

    if (ty == 0) {
        float pz = 0.f, pr = 0.f;
#pragma unroll
        for (int g = 0; g < 32; ++g) { pz += redz[g][tx]; pr += redr[g][tx]; }
        float znew = sz[w] - pz;
        float rnew = pr + g_a[coefIdx] * znew;
        zout[w] = znew;
        rout[w] = rnew;
    }
}

// ---------------- fused Hf = relu(X@W1+b1), weighted partial reduce -----
// grid: (32 n-chunks, 8 batches), block dim3(64,2): tx = row-in-chunk,
// ty selects 32-wide half of HID. v (= g_r[0]) must be ready.
__global__ void hf_kernel(const float* __restrict__ X,
                          const float* __restrict__ W1,
                          const float* __restrict__ b1) {
    __shared__ float w1s[F0_ * HID_];   // 32 KB
    __shared__ float b1s[HID_];
    __shared__ float red[4][32];

    int tx = threadIdx.x;               // 0..63
    int ty = threadIdx.y;               // 0..1
    int tid = ty * 64 + tx;

    for (int i = tid; i < F0_ * HID_; i += 128) w1s[i] = W1[i];
    if (tid < HID_) b1s[tid] = b1[tid];
    __syncthreads();

    int b = blockIdx.y;
    int chunk = blockIdx.x;
    int n = chunk * 64 + tx;
    const float* xr = X + ((size_t)b * N_ + n) * F0_;
    int h0 = ty * 32;

    float acc[32];
#pragma unroll
    for (int h = 0; h < 32; ++h) acc[h] = b1s[h0 + h];

    for (int f0 = 0; f0 < F0_; f0 += 16) {
        float4 xv[4];
#pragma unroll
        for (int i = 0; i < 4; ++i)
            xv[i] = reinterpret_cast<const float4*>(xr + f0)[i];
        const float* xf = reinterpret_cast<const float*>(xv);
#pragma unroll
        for (int i = 0; i < 16; ++i) {
            float x = xf[i];
            const float4* wrow =
                reinterpret_cast<const float4*>(&w1s[(f0 + i) * HID_ + h0]);
#pragma unroll
            for (int q = 0; q < 8; ++q) {
                float4 wv = wrow[q];
                acc[q * 4 + 0] += x * wv.x;
                acc[q * 4 + 1] += x * wv.y;
                acc[q * 4 + 2] += x * wv.z;
                acc[q * 4 + 3] += x * wv.w;
            }
        }
    }

    float s = g_r[0][n] * (1.0f / (float)N_);   // v[n] / N
#pragma unroll
    for (int h = 0; h < 32; ++h) acc[h] = fmaxf(acc[h], 0.f) * s;

    // deterministic reduce over the 64 rows: intra-warp shuffles + shared
#pragma unroll
    for (int h = 0; h < 32; ++h) {
        float v_ = acc[h];
        v_ += __shfl_xor_sync(0xffffffffu, v_, 16);
        v_ += __shfl_xor_sync(0xffffffffu, v_, 8);
        v_ += __shfl_xor_sync(0xffffffffu, v_, 4);
        v_ += __shfl_xor_sync(0xffffffffu, v_, 2);
        v_ += __shfl_xor_sync(0xffffffffu, v_, 1);
        acc[h] = v_;
    }
    int lane = tid & 31, warp = tid >> 5;
    if (lane == 0) {
#pragma unroll
        for (int h = 0; h < 32; ++h) red[warp][h] = acc[h];
    }
    __syncthreads();
    if (tid < 64) {
        int hh = tid & 31;
        int grp = tid >> 5;     // 0 -> warps {0,1} (h 0..31), 1 -> {2,3} (h 32..63)
        g_part[b][chunk][grp * 32 + hh] = red[grp * 2][hh] + red[grp * 2 + 1][hh];
    }
}

// ---------------- final: reduce chunks, logits = Hg@W2 + b2 -------------
__global__ void final_kernel(const float* __restrict__ W2,
                             const float* __restrict__ b2,
                             float* __restrict__ out) {
    __shared__ float hg[B_ * HID_];
    int t = threadIdx.x;                 // 512 threads = (b,h) pairs
    int b = t >> 6, h = t & 63;
    float s = 0.f;
#pragma unroll
    for (int c = 0; c < 32; ++c) s += g_part[b][c][h];
    hg[t] = s;
    __syncthreads();
    if (t < B_ * OUT_) {
        int bb = t >> 4, o = t & 15;
        float acc = b2[o];
#pragma unroll
        for (int hh = 0; hh < HID_; ++hh)
            acc += hg[bb * HID_ + hh] * W2[hh * OUT_ + o];
        out[bb * OUT_ + o] = acc;
    }
}

// ---------------- launcher ----------------------------------------------
extern "C" void kernel_launch(void* const* d_in, const int* in_sizes, int n_in,
                              void* d_out, int out_size) {
    const float* X     = (const float*)d_in[0];
    const float* L     = (const float*)d_in[1];
    const float* W1    = (const float*)d_in[2];
    const float* b1    = (const float*)d_in[3];
    const float* W2    = (const float*)d_in[4];
    const float* b2    = (const float*)d_in[5];
    const float* theta = (const float*)d_in[6];
    float* out = (float*)d_out;

    setup_kernel<<<2, 1024>>>(theta);

    // 10 fused filter passes: pass j consumes parity (j-1)&1, coef a[K-j]
    for (int j = 1; j <= K_; ++j) {
        pass_kernel<<<N_ / 8, dim3(8, 32)>>>(L, (j - 1) & 1, K_ - j);
    }
    // final r lands in parity 0 (j=10 writes pin^1 with pin=1)

    hf_kernel<<<dim3(32, B_), dim3(64, 2)>>>(X, W1, b1);
    final_kernel<<<1, 512>>>(W2, b2, out);
}

// round 3
// speedup vs baseline: 1.2139x; 1.2139x over previous
#include <cuda_runtime.h>
#include <cuda_fp16.h>
#include <cstdint>

// Problem constants
#define B_   8
#define N_   2048
#define F0_  128
#define HID_ 64
#define OUT_ 16
#define K_   10

#define VCHUNKS 32          // 64 rows per chunk
#define ROWS_PER_CHUNK (N_ / VCHUNKS)

// ---------------- device scratch (static; no allocation) ----------------
__device__ __half2 g_Lh[N_ * N_ / 2];     // 8 MB fp16 copy of L (row-major, w pairs)
__device__ float g_z[2][N_];              // ping-pong (I-L^T)^k 1 chain
__device__ float g_r[2][N_];              // ping-pong Horner accumulator
__device__ float g_a[K_ + 1];             // a_i = theta_i * C(K,i)
__device__ float g_pz[VCHUNKS][N_];       // per-chunk partial L^T z
__device__ float g_pr[VCHUNKS][N_];       // per-chunk partial L^T r
__device__ float g_part[B_][32][HID_];    // per-(b,chunk) partial Hg sums

__constant__ float c_binom[K_ + 1] = {1.f, 10.f, 45.f, 120.f, 210.f, 252.f,
                                      210.f, 120.f, 45.f, 10.f, 1.f};

// ---------------- setup: init z0 = 1, r0 = a_K * 1, coefficients --------
__global__ void setup_kernel(const float* __restrict__ theta) {
    int i = blockIdx.x * 1024 + threadIdx.x;
    if (i < N_) {
        g_z[0][i] = 1.0f;
        g_r[0][i] = theta[K_];   // a_K = theta_K * C(K,K)
    }
    if (i < K_ + 1) g_a[i] = theta[i] * c_binom[i];
}

// ---------------- convert L (fp32) -> g_Lh (fp16 pairs) -----------------
// 1M float4 loads; each thread converts 4 floats.
__global__ void convert_kernel(const float* __restrict__ L) {
    int idx = blockIdx.x * 256 + threadIdx.x;       // over N*N/4
    float4 f = reinterpret_cast<const float4*>(L)[idx];
    g_Lh[2 * idx]     = __floats2half2_rn(f.x, f.y);
    g_Lh[2 * idx + 1] = __floats2half2_rn(f.z, f.w);
}

// ---------------- pass phase 1: partial column dots ----------------------
// grid (8 wtiles, 32 vchunks), block 128 threads. Each thread: 2 adjacent w
// (one half2 lane), 64 rows, fully unrolled -> 64 outstanding coalesced loads.
__global__ __launch_bounds__(128) void pass_partial(int pin) {
    __shared__ float szc[ROWS_PER_CHUNK];
    __shared__ float src[ROWS_PER_CHUNK];

    int tx = threadIdx.x;                 // 0..127
    int v0 = blockIdx.y * ROWS_PER_CHUNK;

    if (tx < ROWS_PER_CHUNK) szc[tx] = g_z[pin][v0 + tx];
    else if (tx < 2 * ROWS_PER_CHUNK) src[tx - ROWS_PER_CHUNK] = g_r[pin][v0 + tx - ROWS_PER_CHUNK];
    __syncthreads();

    int w2 = blockIdx.x * 128 + tx;       // half2 column index (covers w=2*w2, 2*w2+1)
    const __half2* Lp = g_Lh + (size_t)v0 * (N_ / 2) + w2;

    float az0 = 0.f, az1 = 0.f, ar0 = 0.f, ar1 = 0.f;
#pragma unroll
    for (int v = 0; v < ROWS_PER_CHUNK; ++v) {
        float2 f = __half22float2(Lp[(size_t)v * (N_ / 2)]);
        float zc = szc[v], rc = src[v];
        az0 += f.x * zc;  az1 += f.y * zc;
        ar0 += f.x * rc;  ar1 += f.y * rc;
    }
    reinterpret_cast<float2*>(g_pz[blockIdx.y])[w2] = make_float2(az0, az1);
    reinterpret_cast<float2*>(g_pr[blockIdx.y])[w2] = make_float2(ar0, ar1);
}

// ---------------- pass phase 2: reduce partials, update z/r --------------
// Fixed summation order -> deterministic. 2048 threads.
__global__ void pass_reduce(int pin, int coefIdx) {
    int w = blockIdx.x * 256 + threadIdx.x;
    float sz = 0.f, sr = 0.f;
#pragma unroll
    for (int c = 0; c < VCHUNKS; ++c) {
        sz += g_pz[c][w];
        sr += g_pr[c][w];
    }
    float znew = g_z[pin][w] - sz;
    float rnew = sr + g_a[coefIdx] * znew;
    g_z[pin ^ 1][w] = znew;
    g_r[pin ^ 1][w] = rnew;
}

// ---------------- fused Hf = relu(X@W1+b1), weighted partial reduce -----
__global__ void hf_kernel(const float* __restrict__ X,
                          const float* __restrict__ W1,
                          const float* __restrict__ b1) {
    __shared__ float w1s[F0_ * HID_];   // 32 KB
    __shared__ float b1s[HID_];
    __shared__ float red[4][32];

    int tx = threadIdx.x;               // 0..63
    int ty = threadIdx.y;               // 0..1
    int tid = ty * 64 + tx;

    for (int i = tid; i < F0_ * HID_; i += 128) w1s[i] = W1[i];
    if (tid < HID_) b1s[tid] = b1[tid];
    __syncthreads();

    int b = blockIdx.y;
    int chunk = blockIdx.x;
    int n = chunk * 64 + tx;
    const float* xr = X + ((size_t)b * N_ + n) * F0_;
    int h0 = ty * 32;

    float acc[32];
#pragma unroll
    for (int h = 0; h < 32; ++h) acc[h] = b1s[h0 + h];

    for (int f0 = 0; f0 < F0_; f0 += 16) {
        float4 xv[4];
#pragma unroll
        for (int i = 0; i < 4; ++i)
            xv[i] = reinterpret_cast<const float4*>(xr + f0)[i];
        const float* xf = reinterpret_cast<const float*>(xv);
#pragma unroll
        for (int i = 0; i < 16; ++i) {
            float x = xf[i];
            const float4* wrow =
                reinterpret_cast<const float4*>(&w1s[(f0 + i) * HID_ + h0]);
#pragma unroll
            for (int q = 0; q < 8; ++q) {
                float4 wv = wrow[q];
                acc[q * 4 + 0] += x * wv.x;
                acc[q * 4 + 1] += x * wv.y;
                acc[q * 4 + 2] += x * wv.z;
                acc[q * 4 + 3] += x * wv.w;
            }
        }
    }

    float s = g_r[0][n] * (1.0f / (float)N_);   // v[n] / N
#pragma unroll
    for (int h = 0; h < 32; ++h) acc[h] = fmaxf(acc[h], 0.f) * s;

#pragma unroll
    for (int h = 0; h < 32; ++h) {
        float v_ = acc[h];
        v_ += __shfl_xor_sync(0xffffffffu, v_, 16);
        v_ += __shfl_xor_sync(0xffffffffu, v_, 8);
        v_ += __shfl_xor_sync(0xffffffffu, v_, 4);
        v_ += __shfl_xor_sync(0xffffffffu, v_, 2);
        v_ += __shfl_xor_sync(0xffffffffu, v_, 1);
        acc[h] = v_;
    }
    int lane = tid & 31, warp = tid >> 5;
    if (lane == 0) {
#pragma unroll
        for (int h = 0; h < 32; ++h) red[warp][h] = acc[h];
    }
    __syncthreads();
    if (tid < 64) {
        int hh = tid & 31;
        int grp = tid >> 5;
        g_part[b][chunk][grp * 32 + hh] = red[grp * 2][hh] + red[grp * 2 + 1][hh];
    }
}

// ---------------- final: reduce chunks, logits = Hg@W2 + b2 -------------
__global__ void final_kernel(const float* __restrict__ W2,
                             const float* __restrict__ b2,
                             float* __restrict__ out) {
    __shared__ float hg[B_ * HID_];
    int t = threadIdx.x;                 // 512 threads = (b,h) pairs
    int b = t >> 6, h = t & 63;
    float s = 0.f;
#pragma unroll
    for (int c = 0; c < 32; ++c) s += g_part[b][c][h];
    hg[t] = s;
    __syncthreads();
    if (t < B_ * OUT_) {
        int bb = t >> 4, o = t & 15;
        float acc = b2[o];
#pragma unroll
        for (int hh = 0; hh < HID_; ++hh)
            acc += hg[bb * HID_ + hh] * W2[hh * OUT_ + o];
        out[bb * OUT_ + o] = acc;
    }
}

// ---------------- launcher ----------------------------------------------
extern "C" void kernel_launch(void* const* d_in, const int* in_sizes, int n_in,
                              void* d_out, int out_size) {
    const float* X     = (const float*)d_in[0];
    const float* L     = (const float*)d_in[1];
    const float* W1    = (const float*)d_in[2];
    const float* b1    = (const float*)d_in[3];
    const float* W2    = (const float*)d_in[4];
    const float* b2    = (const float*)d_in[5];
    const float* theta = (const float*)d_in[6];
    float* out = (float*)d_out;

    setup_kernel<<<2, 1024>>>(theta);
    convert_kernel<<<(N_ * N_ / 4) / 256, 256>>>(L);

    // 10 fused filter passes: pass j consumes parity (j-1)&1, coef a[K-j]
    for (int j = 1; j <= K_; ++j) {
        pass_partial<<<dim3(8, VCHUNKS), 128>>>((j - 1) & 1);
        pass_reduce<<<N_ / 256, 256>>>((j - 1) & 1, K_ - j);
    }
    // final r lands in parity 0

    hf_kernel<<<dim3(32, B_), dim3(64, 2)>>>(X, W1, b1);
    final_kernel<<<1, 512>>>(W2, b2, out);
}